// round 8
// baseline (speedup 1.0000x reference)
#include <cuda_runtime.h>
#include <cuda_bf16.h>
#include <cstdint>

// MeshConv via mma.sync m16n8k16 bf16 split hi/lo (3-term).
// Cooperative full-line gather + shfl-butterfly feature build, warp-independent MMA.

#define NK      160
#define TILE_E  128
#define THREADS 128
#define RSTRIDE 336                      // A row stride bytes (21*16, /16 odd)
#define A_BYTES (TILE_E * RSTRIDE)       // 43008 per split
#define SM_AHI  0
#define SM_ALO  A_BYTES
#define SM_IDX  (2 * A_BYTES)            // 128 elems * 4 ints
#define SM_TOTAL (2 * A_BYTES + TILE_E * 4 * 4)   // 88064 B
#define WF_U4   (10 * 8 * 32)

__device__ uint4 g_Wfrag[WF_U4];
__device__ int   g_nbr64;

__device__ __forceinline__ uint32_t pk_bf16x2(float lo, float hi) {
    uint32_t r;
    asm("cvt.rn.satfinite.bf16x2.f32 %0, %1, %2;" : "=r"(r) : "f"(hi), "f"(lo));
    return r;
}

__global__ void meshconv_prep(const float* __restrict__ W,
                              const void* __restrict__ nbr_raw, int E) {
    int i = blockIdx.x * blockDim.x + threadIdx.x;
    if (i < WF_U4) {
        int lane = i & 31;
        int n    = (i >> 5) & 7;
        int ks   = i >> 8;
        int ng = n * 8 + (lane >> 2);
        int k0 = ks * 16 + (lane & 3) * 2;
        float w00 = W[ng * NK + k0],     w01 = W[ng * NK + k0 + 1];
        float w10 = W[ng * NK + k0 + 8], w11 = W[ng * NK + k0 + 9];
        float h00 = __bfloat162float(__float2bfloat16(w00));
        float h01 = __bfloat162float(__float2bfloat16(w01));
        float h10 = __bfloat162float(__float2bfloat16(w10));
        float h11 = __bfloat162float(__float2bfloat16(w11));
        uint4 f;
        f.x = pk_bf16x2(h00, h01);
        f.y = pk_bf16x2(h10, h11);
        f.z = pk_bf16x2(w00 - h00, w01 - h01);
        f.w = pk_bf16x2(w10 - h10, w11 - h11);
        g_Wfrag[i] = f;
    }
    if (i == 0) {
        const long long* p = (const long long*)nbr_raw;
        int ok = 1;
        #pragma unroll
        for (int j = 0; j < 16; j++) {
            long long v = p[j];
            if (v < -(long long)E || v >= (long long)E) ok = 0;
        }
        g_nbr64 = ok;
    }
}

__device__ __forceinline__ uint32_t smem_u32(const void* p) {
    uint32_t a;
    asm("{ .reg .u64 t; cvta.to.shared.u64 t, %1; cvt.u32.u64 %0, t; }" : "=r"(a) : "l"(p));
    return a;
}
__device__ __forceinline__ void ldsm_x4(uint32_t* r, uint32_t addr) {
    asm volatile("ldmatrix.sync.aligned.m8n8.x4.shared.b16 {%0,%1,%2,%3}, [%4];"
                 : "=r"(r[0]), "=r"(r[1]), "=r"(r[2]), "=r"(r[3]) : "r"(addr));
}
__device__ __forceinline__ void mma_bf16(float* d, const uint32_t* a,
                                         uint32_t b0, uint32_t b1) {
    asm volatile(
        "mma.sync.aligned.m16n8k16.row.col.f32.bf16.bf16.f32 "
        "{%0,%1,%2,%3}, {%4,%5,%6,%7}, {%8,%9}, {%0,%1,%2,%3};"
        : "+f"(d[0]), "+f"(d[1]), "+f"(d[2]), "+f"(d[3])
        : "r"(a[0]), "r"(a[1]), "r"(a[2]), "r"(a[3]), "r"(b0), "r"(b1));
}
// split 2 floats into hi/lo bf16x2 and store 8B each
__device__ __forceinline__ void split_store(char* hiP, char* loP,
                                            float w0, float w1, float w2, float w3) {
    uint32_t h01 = pk_bf16x2(w0, w1);
    uint32_t h23 = pk_bf16x2(w2, w3);
    float e0 = __uint_as_float(h01 << 16), e1 = __uint_as_float(h01 & 0xFFFF0000u);
    float e2 = __uint_as_float(h23 << 16), e3 = __uint_as_float(h23 & 0xFFFF0000u);
    uint32_t l01 = pk_bf16x2(w0 - e0, w1 - e1);
    uint32_t l23 = pk_bf16x2(w2 - e2, w3 - e3);
    *(uint2*)hiP = make_uint2(h01, h23);
    *(uint2*)loP = make_uint2(l01, l23);
}

__global__ __launch_bounds__(THREADS, 2)
void meshconv_kernel(const float* __restrict__ x,
                     const void* __restrict__ nbr_raw,
                     const float* __restrict__ bias,
                     float* __restrict__ out, int E) {
    extern __shared__ char smem[];
    const uint32_t sbase = smem_u32(smem);
    const int tid  = threadIdx.x;
    const int lane = tid & 31;
    const int warp = tid >> 5;
    int* sIdx = (int*)(smem + SM_IDX);

    const int e0 = blockIdx.x * TILE_E;

    // ---- write resolved neighbor indices (negative => masked) ----
    {
        const int er = (e0 + tid) < E ? (e0 + tid) : (E - 1);
        long long n[4];
        if (g_nbr64) {
            const long long* nb = (const long long*)nbr_raw + (size_t)er * 4;
            n[0] = nb[0]; n[1] = nb[1]; n[2] = nb[2]; n[3] = nb[3];
        } else {
            const int* nb = (const int*)nbr_raw + (size_t)er * 4;
            n[0] = nb[0]; n[1] = nb[1]; n[2] = nb[2]; n[3] = nb[3];
        }
        #pragma unroll
        for (int j = 0; j < 4; j++) {
            long long v = n[j];
            int idx = (v < 0) ? -1 : (v >= E ? E - 1 : (int)v);
            sIdx[tid * 4 + j] = idx;
        }
    }
    __syncwarp();

    const int j8 = lane >> 3;     // neighbor slot 0..3
    const int c8 = lane & 7;      // 16B chunk 0..7
    char* aHiW = smem + SM_AHI + (warp * 32) * RSTRIDE;
    char* aLoW = smem + SM_ALO + (warp * 32) * RSTRIDE;

    // ---- x rows (group 0): cooperative coalesced load, split, store ----
    #pragma unroll
    for (int t = 0; t < 8; t++) {
        int r = 4 * t + j8;                       // local row 0..31
        int row = e0 + warp * 32 + r;
        row = row < E ? row : (E - 1);
        float4 v = *(const float4*)(x + (size_t)row * 32 + c8 * 4);
        split_store(aHiW + r * RSTRIDE + c8 * 8,
                    aLoW + r * RSTRIDE + c8 * 8, v.x, v.y, v.z, v.w);
    }

    // ---- neighbor gather + butterfly features (groups 1..4) ----
    const unsigned FULL = 0xFFFFFFFFu;
    #pragma unroll 4
    for (int i = 0; i < 32; i++) {
        int idx = sIdx[(warp * 32 + i) * 4 + j8];
        float msk = idx >= 0 ? 1.0f : 0.0f;
        int row = idx >= 0 ? idx : 0;
        float4 v = *(const float4*)(x + (size_t)row * 32 + c8 * 4);
        float v0 = v.x * msk, v1 = v.y * msk, v2 = v.z * msk, v3 = v.w * msk;

        // xor 8: pair within (a0,a1) / (b0,b1)
        float p0 = __shfl_xor_sync(FULL, v0, 8);
        float p1 = __shfl_xor_sync(FULL, v1, 8);
        float p2 = __shfl_xor_sync(FULL, v2, 8);
        float p3 = __shfl_xor_sync(FULL, v3, 8);
        float s0 = v0 + p0, d0 = fabsf(v0 - p0);
        float s1 = v1 + p1, d1 = fabsf(v1 - p1);
        float s2 = v2 + p2, d2 = fabsf(v2 - p2);
        float s3 = v3 + p3, d3 = fabsf(v3 - p3);

        // xor 16: combine a-side with b-side
        float q0 = __shfl_xor_sync(FULL, s0, 16);
        float q1 = __shfl_xor_sync(FULL, s1, 16);
        float q2 = __shfl_xor_sync(FULL, s2, 16);
        float q3 = __shfl_xor_sync(FULL, s3, 16);
        float r0 = __shfl_xor_sync(FULL, d0, 16);
        float r1 = __shfl_xor_sync(FULL, d1, 16);
        float r2 = __shfl_xor_sync(FULL, d2, 16);
        float r3 = __shfl_xor_sync(FULL, d3, 16);

        float g1_0 = s0 + q0, g3_0 = fabsf(s0 - q0);
        float g1_1 = s1 + q1, g3_1 = fabsf(s1 - q1);
        float g1_2 = s2 + q2, g3_2 = fabsf(s2 - q2);
        float g1_3 = s3 + q3, g3_3 = fabsf(s3 - q3);
        float g2_0 = d0 + r0, g4_0 = fabsf(d0 - r0);
        float g2_1 = d1 + r1, g4_1 = fabsf(d1 - r1);
        float g2_2 = d2 + r2, g4_2 = fabsf(d2 - r2);
        float g2_3 = d3 + r3, g4_3 = fabsf(d3 - r3);

        // lane writes group j8+1, chunk c8 of element i
        float w0 = (j8 == 0) ? g1_0 : (j8 == 1) ? g2_0 : (j8 == 2) ? g3_0 : g4_0;
        float w1 = (j8 == 0) ? g1_1 : (j8 == 1) ? g2_1 : (j8 == 2) ? g3_1 : g4_1;
        float w2 = (j8 == 0) ? g1_2 : (j8 == 1) ? g2_2 : (j8 == 2) ? g3_2 : g4_2;
        float w3 = (j8 == 0) ? g1_3 : (j8 == 1) ? g2_3 : (j8 == 2) ? g3_3 : g4_3;

        int off = i * RSTRIDE + (j8 + 1) * 64 + c8 * 8;
        split_store(aHiW + off, aLoW + off, w0, w1, w2, w3);
    }
    __syncwarp();

    // ---- MMA over own 32 rows ----
    float acc[2][8][4];
    #pragma unroll
    for (int st = 0; st < 2; st++)
        #pragma unroll
        for (int nn = 0; nn < 8; nn++)
            #pragma unroll
            for (int q = 0; q < 4; q++) acc[st][nn][q] = 0.0f;

    const uint32_t arow = (uint32_t)(warp * 32 + (lane & 15));
    const uint32_t aoff = ((uint32_t)(lane >> 4)) * 16;
    const uint32_t ahi0 = sbase + SM_AHI + arow * RSTRIDE + aoff;
    const uint32_t ahi1 = ahi0 + 16 * RSTRIDE;
    const uint32_t alo0 = sbase + SM_ALO + arow * RSTRIDE + aoff;
    const uint32_t alo1 = alo0 + 16 * RSTRIDE;

    #pragma unroll
    for (int ks = 0; ks < 10; ks++) {
        uint32_t fh0[4], fh1[4], fl0[4], fl1[4];
        ldsm_x4(fh0, ahi0 + ks * 32);
        ldsm_x4(fh1, ahi1 + ks * 32);
        ldsm_x4(fl0, alo0 + ks * 32);
        ldsm_x4(fl1, alo1 + ks * 32);
        #pragma unroll
        for (int nn = 0; nn < 8; nn++) {
            uint4 f = __ldg(&g_Wfrag[(ks * 8 + nn) * 32 + lane]);
            mma_bf16(acc[0][nn], fh0, f.x, f.y);
            mma_bf16(acc[0][nn], fh0, f.z, f.w);
            mma_bf16(acc[0][nn], fl0, f.x, f.y);
            mma_bf16(acc[1][nn], fh1, f.x, f.y);
            mma_bf16(acc[1][nn], fh1, f.z, f.w);
            mma_bf16(acc[1][nn], fl1, f.x, f.y);
        }
    }

    // ---- Epilogue ----
    const int colq = (lane & 3) * 2;
    #pragma unroll
    for (int nn = 0; nn < 8; nn++) {
        int col = nn * 8 + colq;
        float2 bv = *(const float2*)(bias + col);
        #pragma unroll
        for (int st = 0; st < 2; st++) {
            int rbase = e0 + warp * 32 + st * 16 + (lane >> 2);
            if (rbase < E) {
                float2 o0 = make_float2(acc[st][nn][0] + bv.x, acc[st][nn][1] + bv.y);
                *(float2*)(out + (size_t)rbase * 64 + col) = o0;
            }
            if (rbase + 8 < E) {
                float2 o1 = make_float2(acc[st][nn][2] + bv.x, acc[st][nn][3] + bv.y);
                *(float2*)(out + (size_t)(rbase + 8) * 64 + col) = o1;
            }
        }
    }
}

extern "C" void kernel_launch(void* const* d_in, const int* in_sizes, int n_in,
                              void* d_out, int out_size) {
    const int E = out_size / 64;
    const float* x = nullptr; const void* nbr = nullptr;
    const float* W = nullptr; const float* b = nullptr;

    for (int i = 0; i < n_in; i++) {
        long long sz = in_sizes[i];
        if (sz == (long long)E * 32)      x   = (const float*)d_in[i];
        else if (sz == (long long)E * 4)  nbr = d_in[i];
        else if (sz == 64 * NK)           W   = (const float*)d_in[i];
        else if (sz == 64)                b   = (const float*)d_in[i];
    }
    float* out = (float*)d_out;

    meshconv_prep<<<(WF_U4 + 255) / 256, 256>>>(W, nbr, E);

    cudaFuncSetAttribute(meshconv_kernel,
                         cudaFuncAttributeMaxDynamicSharedMemorySize, SM_TOTAL);
    int nb = (E + TILE_E - 1) / TILE_E;
    meshconv_kernel<<<nb, THREADS, SM_TOTAL>>>(x, nbr, b, out, E);
}

// round 10
// speedup vs baseline: 2.6780x; 2.6780x over previous
#include <cuda_runtime.h>
#include <cuda_bf16.h>
#include <cstdint>

// MeshConv via mma.sync m16n8k16 bf16 split hi/lo (3-term), warp-independent.
// cp.async full-line cooperative gather (zero-masked in flight) -> local
// feature build (no shuffles) -> ldsm/MMA (R7 skeleton).

#define NK      160
#define TILE_E  128
#define THREADS 128
#define RSTRIDE 336                      // A row stride bytes
#define A_BYTES (TILE_E * RSTRIDE)       // 43008 per split
#define EFOOT   592                      // scratch bytes per element
#define SCR_W   (8 * EFOOT)              // 4736 per warp
#define SM_AHI  0
#define SM_ALO  A_BYTES
#define SM_SCR  (2 * A_BYTES)            // 86016
#define SM_IDX  (SM_SCR + 4 * SCR_W)     // 104960
#define SM_TOTAL (SM_IDX + TILE_E * 4 * 4)   // 107008
#define WF_U4   (10 * 8 * 32)

__device__ uint4 g_Wfrag[WF_U4];
__device__ int   g_nbr64;

__device__ __forceinline__ uint32_t pk_bf16x2(float lo, float hi) {
    uint32_t r;
    asm("cvt.rn.satfinite.bf16x2.f32 %0, %1, %2;" : "=r"(r) : "f"(hi), "f"(lo));
    return r;
}

__global__ void meshconv_prep(const float* __restrict__ W,
                              const void* __restrict__ nbr_raw, int E) {
    int i = blockIdx.x * blockDim.x + threadIdx.x;
    if (i < WF_U4) {
        int lane = i & 31;
        int n    = (i >> 5) & 7;
        int ks   = i >> 8;
        int ng = n * 8 + (lane >> 2);
        int k0 = ks * 16 + (lane & 3) * 2;
        float w00 = W[ng * NK + k0],     w01 = W[ng * NK + k0 + 1];
        float w10 = W[ng * NK + k0 + 8], w11 = W[ng * NK + k0 + 9];
        float h00 = __bfloat162float(__float2bfloat16(w00));
        float h01 = __bfloat162float(__float2bfloat16(w01));
        float h10 = __bfloat162float(__float2bfloat16(w10));
        float h11 = __bfloat162float(__float2bfloat16(w11));
        uint4 f;
        f.x = pk_bf16x2(h00, h01);
        f.y = pk_bf16x2(h10, h11);
        f.z = pk_bf16x2(w00 - h00, w01 - h01);
        f.w = pk_bf16x2(w10 - h10, w11 - h11);
        g_Wfrag[i] = f;
    }
    if (i == 0) {
        const long long* p = (const long long*)nbr_raw;
        int ok = 1;
        #pragma unroll
        for (int j = 0; j < 16; j++) {
            long long v = p[j];
            if (v < -(long long)E || v >= (long long)E) ok = 0;
        }
        g_nbr64 = ok;
    }
}

__device__ __forceinline__ uint32_t smem_u32(const void* p) {
    uint32_t a;
    asm("{ .reg .u64 t; cvta.to.shared.u64 t, %1; cvt.u32.u64 %0, t; }" : "=r"(a) : "l"(p));
    return a;
}
__device__ __forceinline__ void ldsm_x4(uint32_t* r, uint32_t addr) {
    asm volatile("ldmatrix.sync.aligned.m8n8.x4.shared.b16 {%0,%1,%2,%3}, [%4];"
                 : "=r"(r[0]), "=r"(r[1]), "=r"(r[2]), "=r"(r[3]) : "r"(addr));
}
__device__ __forceinline__ void mma_bf16(float* d, const uint32_t* a,
                                         uint32_t b0, uint32_t b1) {
    asm volatile(
        "mma.sync.aligned.m16n8k16.row.col.f32.bf16.bf16.f32 "
        "{%0,%1,%2,%3}, {%4,%5,%6,%7}, {%8,%9}, {%0,%1,%2,%3};"
        : "+f"(d[0]), "+f"(d[1]), "+f"(d[2]), "+f"(d[3])
        : "r"(a[0]), "r"(a[1]), "r"(a[2]), "r"(a[3]), "r"(b0), "r"(b1));
}
__device__ __forceinline__ void cp_async16(uint32_t dst, const void* src, int srcsz) {
    asm volatile("cp.async.cg.shared.global [%0], [%1], 16, %2;"
                 :: "r"(dst), "l"(src), "r"(srcsz) : "memory");
}
// 4 floats -> 8B hi bf16x2 pair + 8B lo bf16x2 pair
__device__ __forceinline__ void split_store(char* hiP, char* loP,
                                            float w0, float w1, float w2, float w3) {
    uint32_t h01 = pk_bf16x2(w0, w1);
    uint32_t h23 = pk_bf16x2(w2, w3);
    float e0 = __uint_as_float(h01 << 16), e1 = __uint_as_float(h01 & 0xFFFF0000u);
    float e2 = __uint_as_float(h23 << 16), e3 = __uint_as_float(h23 & 0xFFFF0000u);
    uint32_t l01 = pk_bf16x2(w0 - e0, w1 - e1);
    uint32_t l23 = pk_bf16x2(w2 - e2, w3 - e3);
    *(uint2*)hiP = make_uint2(h01, h23);
    *(uint2*)loP = make_uint2(l01, l23);
}

__global__ __launch_bounds__(THREADS, 2)
void meshconv_kernel(const float* __restrict__ x,
                     const void* __restrict__ nbr_raw,
                     const float* __restrict__ bias,
                     float* __restrict__ out, int E) {
    extern __shared__ char smem[];
    const uint32_t sbase = smem_u32(smem);
    const int tid  = threadIdx.x;
    const int lane = tid & 31;
    const int warp = tid >> 5;
    int* sIdx = (int*)(smem + SM_IDX);

    const int e0 = blockIdx.x * TILE_E;

    // ---- resolve neighbor indices for own element ----
    {
        const int er = (e0 + tid) < E ? (e0 + tid) : (E - 1);
        long long n[4];
        if (g_nbr64) {
            const long long* nb = (const long long*)nbr_raw + (size_t)er * 4;
            n[0] = nb[0]; n[1] = nb[1]; n[2] = nb[2]; n[3] = nb[3];
        } else {
            const int* nb = (const int*)nbr_raw + (size_t)er * 4;
            n[0] = nb[0]; n[1] = nb[1]; n[2] = nb[2]; n[3] = nb[3];
        }
        int4 w;
        w.x = (n[0] < 0) ? -1 : (n[0] >= E ? E - 1 : (int)n[0]);
        w.y = (n[1] < 0) ? -1 : (n[1] >= E ? E - 1 : (int)n[1]);
        w.z = (n[2] < 0) ? -1 : (n[2] >= E ? E - 1 : (int)n[2]);
        w.w = (n[3] < 0) ? -1 : (n[3] >= E ? E - 1 : (int)n[3]);
        *(int4*)(sIdx + tid * 4) = w;
    }
    __syncwarp();

    const int j8 = lane >> 3, c8 = lane & 7;     // gather roles
    const int el = lane & 7,  sl = lane >> 3;    // compute roles
    const uint32_t scr = sbase + SM_SCR + warp * SCR_W;
    char* scrp = smem + SM_SCR + warp * SCR_W;
    char* aHiW = smem + SM_AHI;
    char* aLoW = smem + SM_ALO;

    #pragma unroll
    for (int ch = 0; ch < 4; ch++) {
        // ---- cooperative full-line gather: 8 elements x 4 neighbor rows ----
        #pragma unroll
        for (int i = 0; i < 8; i++) {
            int eg  = warp * 32 + ch * 8 + i;
            int idx = sIdx[eg * 4 + j8];
            const float* src = x + (size_t)(idx < 0 ? 0 : idx) * 32 + c8 * 4;
            cp_async16(scr + i * EFOOT + j8 * 144 + c8 * 16, src, idx < 0 ? 0 : 16);
        }
        asm volatile("cp.async.commit_group;" ::: "memory");
        asm volatile("cp.async.wait_group 0;" ::: "memory");
        __syncwarp();

        // ---- local feature build: lane owns (element el, channel slice sl) ----
        const int egl = warp * 32 + ch * 8 + el;
        const int erg = (e0 + egl) < E ? (e0 + egl) : (E - 1);

        float4 a0l = *(const float4*)(scrp + el * EFOOT + 0 * 144 + sl * 32);
        float4 a0h = *(const float4*)(scrp + el * EFOOT + 0 * 144 + sl * 32 + 16);
        float4 a1l = *(const float4*)(scrp + el * EFOOT + 1 * 144 + sl * 32);
        float4 a1h = *(const float4*)(scrp + el * EFOOT + 1 * 144 + sl * 32 + 16);
        float4 b0l = *(const float4*)(scrp + el * EFOOT + 2 * 144 + sl * 32);
        float4 b0h = *(const float4*)(scrp + el * EFOOT + 2 * 144 + sl * 32 + 16);
        float4 b1l = *(const float4*)(scrp + el * EFOOT + 3 * 144 + sl * 32);
        float4 b1h = *(const float4*)(scrp + el * EFOOT + 3 * 144 + sl * 32 + 16);
        float4 xv0 = __ldg((const float4*)(x + (size_t)erg * 32 + sl * 8));
        float4 xv1 = __ldg((const float4*)(x + (size_t)erg * 32 + sl * 8 + 4));

        float A0[8] = {a0l.x,a0l.y,a0l.z,a0l.w,a0h.x,a0h.y,a0h.z,a0h.w};
        float A1[8] = {a1l.x,a1l.y,a1l.z,a1l.w,a1h.x,a1h.y,a1h.z,a1h.w};
        float B0[8] = {b0l.x,b0l.y,b0l.z,b0l.w,b0h.x,b0h.y,b0h.z,b0h.w};
        float B1[8] = {b1l.x,b1l.y,b1l.z,b1l.w,b1h.x,b1h.y,b1h.z,b1h.w};
        float XV[8] = {xv0.x,xv0.y,xv0.z,xv0.w,xv1.x,xv1.y,xv1.z,xv1.w};

        float g1[8], g2[8], g3[8], g4[8];
        #pragma unroll
        for (int j = 0; j < 8; j++) {
            float sa = A0[j] + A1[j], sb = B0[j] + B1[j];
            float da = fabsf(A0[j] - A1[j]), db = fabsf(B0[j] - B1[j]);
            g1[j] = sa + sb;
            g2[j] = da + db;
            g3[j] = fabsf(sa - sb);
            g4[j] = fabsf(da - db);
        }

        // channel slice sl of group g lives at byte offset g*64 + sl*16 (+0/+8)
        char* hrow = aHiW + egl * RSTRIDE + sl * 16;
        char* lrow = aLoW + egl * RSTRIDE + sl * 16;
        split_store(hrow + 0*64 + 0, lrow + 0*64 + 0, XV[0], XV[1], XV[2], XV[3]);
        split_store(hrow + 0*64 + 8, lrow + 0*64 + 8, XV[4], XV[5], XV[6], XV[7]);
        split_store(hrow + 1*64 + 0, lrow + 1*64 + 0, g1[0], g1[1], g1[2], g1[3]);
        split_store(hrow + 1*64 + 8, lrow + 1*64 + 8, g1[4], g1[5], g1[6], g1[7]);
        split_store(hrow + 2*64 + 0, lrow + 2*64 + 0, g2[0], g2[1], g2[2], g2[3]);
        split_store(hrow + 2*64 + 8, lrow + 2*64 + 8, g2[4], g2[5], g2[6], g2[7]);
        split_store(hrow + 3*64 + 0, lrow + 3*64 + 0, g3[0], g3[1], g3[2], g3[3]);
        split_store(hrow + 3*64 + 8, lrow + 3*64 + 8, g3[4], g3[5], g3[6], g3[7]);
        split_store(hrow + 4*64 + 0, lrow + 4*64 + 0, g4[0], g4[1], g4[2], g4[3]);
        split_store(hrow + 4*64 + 8, lrow + 4*64 + 8, g4[4], g4[5], g4[6], g4[7]);
        __syncwarp();   // scratch reuse next chunk
    }

    // ---- MMA over own 32 rows ----
    float acc[2][8][4];
    #pragma unroll
    for (int st = 0; st < 2; st++)
        #pragma unroll
        for (int nn = 0; nn < 8; nn++)
            #pragma unroll
            for (int q = 0; q < 4; q++) acc[st][nn][q] = 0.0f;

    const uint32_t arow = (uint32_t)(warp * 32 + (lane & 15));
    const uint32_t aoff = ((uint32_t)(lane >> 4)) * 16;
    const uint32_t ahi0 = sbase + SM_AHI + arow * RSTRIDE + aoff;
    const uint32_t ahi1 = ahi0 + 16 * RSTRIDE;
    const uint32_t alo0 = sbase + SM_ALO + arow * RSTRIDE + aoff;
    const uint32_t alo1 = alo0 + 16 * RSTRIDE;

    #pragma unroll
    for (int ks = 0; ks < 10; ks++) {
        uint32_t fh0[4], fh1[4], fl0[4], fl1[4];
        ldsm_x4(fh0, ahi0 + ks * 32);
        ldsm_x4(fh1, ahi1 + ks * 32);
        ldsm_x4(fl0, alo0 + ks * 32);
        ldsm_x4(fl1, alo1 + ks * 32);
        #pragma unroll
        for (int nn = 0; nn < 8; nn++) {
            uint4 f = __ldg(&g_Wfrag[(ks * 8 + nn) * 32 + lane]);
            mma_bf16(acc[0][nn], fh0, f.x, f.y);
            mma_bf16(acc[0][nn], fh0, f.z, f.w);
            mma_bf16(acc[0][nn], fl0, f.x, f.y);
            mma_bf16(acc[1][nn], fh1, f.x, f.y);
            mma_bf16(acc[1][nn], fh1, f.z, f.w);
            mma_bf16(acc[1][nn], fl1, f.x, f.y);
        }
    }

    // ---- Epilogue ----
    const int colq = (lane & 3) * 2;
    #pragma unroll
    for (int nn = 0; nn < 8; nn++) {
        int col = nn * 8 + colq;
        float2 bv = *(const float2*)(bias + col);
        #pragma unroll
        for (int st = 0; st < 2; st++) {
            int rbase = e0 + warp * 32 + st * 16 + (lane >> 2);
            if (rbase < E) {
                float2 o0 = make_float2(acc[st][nn][0] + bv.x, acc[st][nn][1] + bv.y);
                *(float2*)(out + (size_t)rbase * 64 + col) = o0;
            }
            if (rbase + 8 < E) {
                float2 o1 = make_float2(acc[st][nn][2] + bv.x, acc[st][nn][3] + bv.y);
                *(float2*)(out + (size_t)(rbase + 8) * 64 + col) = o1;
            }
        }
    }
}

extern "C" void kernel_launch(void* const* d_in, const int* in_sizes, int n_in,
                              void* d_out, int out_size) {
    const int E = out_size / 64;
    const float* x = nullptr; const void* nbr = nullptr;
    const float* W = nullptr; const float* b = nullptr;

    for (int i = 0; i < n_in; i++) {
        long long sz = in_sizes[i];
        if (sz == (long long)E * 32)      x   = (const float*)d_in[i];
        else if (sz == (long long)E * 4)  nbr = d_in[i];
        else if (sz == 64 * NK)           W   = (const float*)d_in[i];
        else if (sz == 64)                b   = (const float*)d_in[i];
    }
    float* out = (float*)d_out;

    meshconv_prep<<<(WF_U4 + 255) / 256, 256>>>(W, nbr, E);

    cudaFuncSetAttribute(meshconv_kernel,
                         cudaFuncAttributeMaxDynamicSharedMemorySize, SM_TOTAL);
    int nb = (E + TILE_E - 1) / TILE_E;
    meshconv_kernel<<<nb, THREADS, SM_TOTAL>>>(x, nbr, b, out, E);
}